// round 11
// baseline (speedup 1.0000x reference)
#include <cuda_runtime.h>
#include <cuda_bf16.h>
#include <mma.h>
#include <math.h>
#include <stdint.h>

using namespace nvcuda;
typedef __nv_bfloat16 bf16;

// Problem constants
#define BQ   8
#define SEQ  1024
#define CH   512
#define HIDC 2048
#define NHD  8
#define HDIM 64
#define ROWS (BQ*SEQ)          // 8192
#define QKVW (3*CH)            // 1536

// ---------------- scratch ----------------------------------------------------
__device__ bf16  g_wqkv[QKVW*CH];
__device__ bf16  g_wproj[CH*CH];
__device__ bf16  g_wfc1[HIDC*CH];
__device__ bf16  g_wfc2[CH*HIDC];
__device__ bf16  g_ln16[ROWS*CH];
__device__ bf16  g_qkv16[(size_t)ROWS*QKVW];
__device__ bf16  g_at16[ROWS*CH];
__device__ float g_x1 [ROWS*CH];
__device__ bf16  g_h16 [(size_t)ROWS*HIDC];
__device__ bf16  g_h216[(size_t)ROWS*HIDC];

// ---------------- helpers ---------------------------------------------------
__device__ __forceinline__ uint32_t su32(const void* p) {
    uint32_t a;
    asm("{ .reg .u64 t; cvta.to.shared.u64 t, %1; cvt.u32.u64 %0, t; }"
        : "=r"(a) : "l"(p));
    return a;
}
#define CPA16(d, s) asm volatile("cp.async.cg.shared.global [%0], [%1], 16;" :: "r"(d), "l"(s))
#define CPCOMMIT()  asm volatile("cp.async.commit_group;" ::: "memory")
#define CPWAIT(n)   asm volatile("cp.async.wait_group %0;" :: "n"(n) : "memory")

// ---------------- fp32 -> bf16 convert --------------------------------------
__global__ void to_bf16(const float* __restrict__ s, bf16* __restrict__ d)
{
    size_t i = ((size_t)blockIdx.x * 256 + threadIdx.x) * 4;
    float4 v = *(const float4*)(s + i);
    bf16 t[4] = { __float2bfloat16(v.x), __float2bfloat16(v.y),
                  __float2bfloat16(v.z), __float2bfloat16(v.w) };
    *(uint2*)(d + i) = *(uint2*)t;
}

// ---------------- LayerNorm (fp32 in, bf16 out) -----------------------------
__global__ void ln_kernel(const float* __restrict__ x,
                          const float* __restrict__ g,
                          const float* __restrict__ b,
                          bf16* __restrict__ out)
{
    int row = blockIdx.x;
    const float* xr = x + (size_t)row * CH;
    bf16* orow = out + (size_t)row * CH;
    int t = threadIdx.x;
    float v[4];
    float s = 0.f;
#pragma unroll
    for (int i = 0; i < 4; i++) { v[i] = xr[t + i*128]; s += v[i]; }
    __shared__ float red[4];
#pragma unroll
    for (int o = 16; o > 0; o >>= 1) s += __shfl_xor_sync(0xffffffffu, s, o);
    if ((t & 31) == 0) red[t >> 5] = s;
    __syncthreads();
    float mean = (red[0] + red[1] + red[2] + red[3]) * (1.0f / CH);
    float vs = 0.f;
#pragma unroll
    for (int i = 0; i < 4; i++) { float d = v[i] - mean; vs += d * d; }
#pragma unroll
    for (int o = 16; o > 0; o >>= 1) vs += __shfl_xor_sync(0xffffffffu, vs, o);
    __syncthreads();
    if ((t & 31) == 0) red[t >> 5] = vs;
    __syncthreads();
    float var = (red[0] + red[1] + red[2] + red[3]) * (1.0f / CH);
    float rstd = rsqrtf(var + 1e-5f);
#pragma unroll
    for (int i = 0; i < 4; i++) {
        int c = t + i*128;
        orow[c] = __float2bfloat16((v[i] - mean) * rstd * g[c] + b[c]);
    }
}

// ---------------- bf16 WMMA GEMM, 3-stage cp.async pipeline -----------------
// out = A @ B^T (+bias)(+res). A [M,K] bf16 rm, B [N,K] bf16 rm.
// CTA 128x128, 8 warps (2m x 4n), warp 64x32. K-chunk 64, 3 stages.
#define LDSB 72                 // bf16 elems per smem row (144B)
#define TILE_E (128*LDSB)       // elems per matrix per stage
#define GT_SMEM (6*TILE_E*2)    // 3 stages x (A+B) x 2B = 110592

template<typename OutT>
__global__ __launch_bounds__(256, 2)
void gemm_bf(const bf16* __restrict__ A, int lda,
             const bf16* __restrict__ B, int ldb,
             const float* __restrict__ bias,
             const float* __restrict__ res, int ldres,
             OutT* __restrict__ out, int ldo, int K)
{
    extern __shared__ char dsmc[];
    bf16* As = (bf16*)dsmc;              // [3][128][LDSB]
    bf16* Bs = As + 3*TILE_E;

    int tid = threadIdx.x;
    int wid = tid >> 5;
    int wm = wid >> 2;
    int wn = wid & 3;
    int m0 = blockIdx.y * 128;
    int n0 = blockIdx.x * 128;

    wmma::fragment<wmma::accumulator, 16, 16, 16, float> fc[4][2];
#pragma unroll
    for (int i = 0; i < 4; i++)
#pragma unroll
        for (int j = 0; j < 2; j++)
            wmma::fill_fragment(fc[i][j], 0.0f);

    int lrow  = tid >> 1;               // 0..127
    int sbase = (tid & 1) * 4;          // 4 segs of 8 elems

    int nK = K / 64;

    auto issue = [&](int kc) {
        int st = kc % 3;
        int k0 = kc * 64;
#pragma unroll
        for (int j = 0; j < 4; j++) {
            int cseg = (sbase + j) * 8;
            CPA16(su32(&As[st * TILE_E + lrow * LDSB + cseg]),
                  A + (size_t)(m0 + lrow) * lda + k0 + cseg);
            CPA16(su32(&Bs[st * TILE_E + lrow * LDSB + cseg]),
                  B + (size_t)(n0 + lrow) * ldb + k0 + cseg);
        }
        CPCOMMIT();
    };

    issue(0);
    if (nK > 1) issue(1);

    for (int kc = 0; kc < nK; kc++) {
        if (kc + 1 < nK) CPWAIT(1); else CPWAIT(0);
        __syncthreads();
        if (kc + 2 < nK) issue(kc + 2);

        int st = kc % 3;
        bf16* Ac = As + st * TILE_E;
        bf16* Bc = Bs + st * TILE_E;
#pragma unroll
        for (int ks = 0; ks < 4; ks++) {
            wmma::fragment<wmma::matrix_a, 16, 16, 16, bf16, wmma::row_major> fa[4];
            wmma::fragment<wmma::matrix_b, 16, 16, 16, bf16, wmma::col_major> fb[2];
#pragma unroll
            for (int i = 0; i < 4; i++)
                wmma::load_matrix_sync(fa[i], &Ac[(wm * 64 + i * 16) * LDSB + ks * 16], LDSB);
#pragma unroll
            for (int j = 0; j < 2; j++)
                wmma::load_matrix_sync(fb[j], &Bc[(wn * 32 + j * 16) * LDSB + ks * 16], LDSB);
#pragma unroll
            for (int i = 0; i < 4; i++)
#pragma unroll
                for (int j = 0; j < 2; j++)
                    wmma::mma_sync(fc[i][j], fa[i], fb[j], fc[i][j]);
        }
        __syncthreads();
    }

    // epilogue through smem (reuse tile space), fused bias/res
    float* eps = (float*)dsmc;          // [128][132]
#pragma unroll
    for (int i = 0; i < 4; i++)
#pragma unroll
        for (int j = 0; j < 2; j++)
            wmma::store_matrix_sync(&eps[(wm * 64 + i * 16) * 132 + wn * 32 + j * 16],
                                    fc[i][j], 132, wmma::mem_row_major);
    __syncthreads();

    int r = tid >> 1;
    int c0 = (tid & 1) * 64;
#pragma unroll
    for (int c = 0; c < 64; c += 4) {
        float4 v = *(float4*)&eps[r * 132 + c0 + c];
        int n = n0 + c0 + c;
        if (bias) {
            v.x += bias[n]; v.y += bias[n + 1]; v.z += bias[n + 2]; v.w += bias[n + 3];
        }
        if (res) {
            float4 rr = *(const float4*)(res + (size_t)(m0 + r) * ldres + n);
            v.x += rr.x; v.y += rr.y; v.z += rr.z; v.w += rr.w;
        }
        if constexpr (sizeof(OutT) == 4) {
            *(float4*)((float*)out + (size_t)(m0 + r) * ldo + n) = v;
        } else {
            bf16 t[4] = { __float2bfloat16(v.x), __float2bfloat16(v.y),
                          __float2bfloat16(v.z), __float2bfloat16(v.w) };
            *(uint2*)((bf16*)out + (size_t)(m0 + r) * ldo + n) = *(uint2*)t;
        }
    }
}

// ---------------- Flash attention, bf16 wmma, cp.async K/V prefetch ---------
// CTA: 64 queries x one head; 256 threads (8 warps). K/V double-buffered.
#define FTILE (64*LDSB*2)               // bytes per bf16 64x72 tile
#define FQS  0
#define FKS0 FTILE
#define FKS1 (2*FTILE)
#define FVS0 (3*FTILE)
#define FVS1 (4*FTILE)
#define FPB  (5*FTILE)
#define FSS  (6*FTILE)                  // fp32 [64][68]
#define FOS  (FSS + 64*68*4)
#define FMLX (FOS + 64*68*4)
#define FLASH_SMEM (FMLX + 512)

__global__ __launch_bounds__(256, 2)
void flash_bf(const bf16* __restrict__ qkv, bf16* __restrict__ out)
{
    extern __shared__ char fsc[];
    bf16*  Qs = (bf16*)(fsc + FQS);     // [64][LDSB]
    bf16*  Kb[2] = { (bf16*)(fsc + FKS0), (bf16*)(fsc + FKS1) };
    bf16*  Vb[2] = { (bf16*)(fsc + FVS0), (bf16*)(fsc + FVS1) };
    bf16*  Pb = (bf16*)(fsc + FPB);
    float* Ss = (float*)(fsc + FSS);    // [64][68]
    float* Os = (float*)(fsc + FOS);    // [64][68]
    float* m_s = (float*)(fsc + FMLX);
    float* l_s = m_s + 64;

    int bz = blockIdx.y;
    int bI = bz / NHD, hI = bz % NHD;
    int q0 = blockIdx.x * 64;
    const bf16* base = qkv + (size_t)bI * SEQ * QKVW + hI * 3 * HDIM;

    int tid = threadIdx.x;
    int wid = tid >> 5;
    int lrow = tid >> 2;                // 0..63
    int lc0  = (tid & 3) * 16;          // 0,16,32,48

    auto issue_kv = [&](int t0) {
        int buf = (t0 >> 6) & 1;
        const bf16* kp = base + (size_t)(t0 + lrow) * QKVW + HDIM + lc0;
        const bf16* vp = base + (size_t)(t0 + lrow) * QKVW + 2 * HDIM + lc0;
        CPA16(su32(&Kb[buf][lrow * LDSB + lc0]),     kp);
        CPA16(su32(&Kb[buf][lrow * LDSB + lc0 + 8]), kp + 8);
        CPA16(su32(&Vb[buf][lrow * LDSB + lc0]),     vp);
        CPA16(su32(&Vb[buf][lrow * LDSB + lc0 + 8]), vp + 8);
        CPCOMMIT();
    };

    {
        const bf16* src = base + (size_t)(q0 + lrow) * QKVW + lc0;
        *(uint4*)&Qs[lrow * LDSB + lc0]     = *(const uint4*)(src);
        *(uint4*)&Qs[lrow * LDSB + lc0 + 8] = *(const uint4*)(src + 8);
        float4 z = {0.f, 0.f, 0.f, 0.f};
        *(float4*)&Os[lrow * 68 + lc0]      = z;
        *(float4*)&Os[lrow * 68 + lc0 + 4]  = z;
        *(float4*)&Os[lrow * 68 + lc0 + 8]  = z;
        *(float4*)&Os[lrow * 68 + lc0 + 12] = z;
        if (tid < 64) { m_s[tid] = -1e30f; l_s[tid] = 0.f; }
    }
    issue_kv(0);

    for (int t0 = 0; t0 < SEQ; t0 += 64) {
        if (t0 + 64 < SEQ) CPWAIT(1); else CPWAIT(0);
        __syncthreads();
        if (t0 + 64 < SEQ) issue_kv(t0 + 64);

        int buf = (t0 >> 6) & 1;
        bf16* Ks = Kb[buf];
        bf16* Vs = Vb[buf];

        // S = Q @ K^T  (64x64, K=64): 8 warps x 2 tiles
#pragma unroll
        for (int t = 0; t < 2; t++) {
            int tt = wid * 2 + t;
            int ti = tt >> 2, tj = tt & 3;
            wmma::fragment<wmma::accumulator, 16, 16, 16, float> sc;
            wmma::fill_fragment(sc, 0.0f);
#pragma unroll
            for (int kf = 0; kf < 4; kf++) {
                wmma::fragment<wmma::matrix_a, 16, 16, 16, bf16, wmma::row_major> fa;
                wmma::fragment<wmma::matrix_b, 16, 16, 16, bf16, wmma::col_major> fb;
                wmma::load_matrix_sync(fa, &Qs[(ti * 16) * LDSB + kf * 16], LDSB);
                wmma::load_matrix_sync(fb, &Ks[(tj * 16) * LDSB + kf * 16], LDSB);
                wmma::mma_sync(sc, fa, fb, sc);
            }
            wmma::store_matrix_sync(&Ss[(ti * 16) * 68 + tj * 16], sc, 68, wmma::mem_row_major);
        }
        __syncthreads();

        // online softmax (fp32), write P to bf16
        {
            float* srow = &Ss[lrow * 68 + lc0];
            float mx = -1e30f;
#pragma unroll
            for (int c = 0; c < 16; c++) mx = fmaxf(mx, srow[c]);
            mx *= 0.125f;
            mx = fmaxf(mx, __shfl_xor_sync(0xffffffffu, mx, 1));
            mx = fmaxf(mx, __shfl_xor_sync(0xffffffffu, mx, 2));
            float mold = m_s[lrow];
            float mnew = fmaxf(mold, mx);
            float sf = __expf(mold - mnew);
            float sum = 0.f;
            bf16* prow = &Pb[lrow * LDSB + lc0];
#pragma unroll
            for (int c = 0; c < 16; c++) {
                float p = __expf(srow[c] * 0.125f - mnew);
                prow[c] = __float2bfloat16(p);
                sum += p;
            }
            sum += __shfl_xor_sync(0xffffffffu, sum, 1);
            sum += __shfl_xor_sync(0xffffffffu, sum, 2);
            float* orow = &Os[lrow * 68 + lc0];
#pragma unroll
            for (int c = 0; c < 16; c++) orow[c] *= sf;
            if ((tid & 3) == 0) {
                m_s[lrow] = mnew;
                l_s[lrow] = l_s[lrow] * sf + sum;
            }
        }
        __syncthreads();

        // O += P @ V (K=64)
#pragma unroll
        for (int t = 0; t < 2; t++) {
            int tt = wid * 2 + t;
            int ti = tt >> 2, tj = tt & 3;
            wmma::fragment<wmma::accumulator, 16, 16, 16, float> oc;
            wmma::load_matrix_sync(oc, &Os[(ti * 16) * 68 + tj * 16], 68, wmma::mem_row_major);
#pragma unroll
            for (int kf = 0; kf < 4; kf++) {
                wmma::fragment<wmma::matrix_a, 16, 16, 16, bf16, wmma::row_major> fa;
                wmma::fragment<wmma::matrix_b, 16, 16, 16, bf16, wmma::row_major> fb;
                wmma::load_matrix_sync(fa, &Pb[(ti * 16) * LDSB + kf * 16], LDSB);
                wmma::load_matrix_sync(fb, &Vs[(kf * 16) * LDSB + tj * 16], LDSB);
                wmma::mma_sync(oc, fa, fb, oc);
            }
            wmma::store_matrix_sync(&Os[(ti * 16) * 68 + tj * 16], oc, 68, wmma::mem_row_major);
        }
    }
    __syncthreads();

    {
        float inv = 1.0f / l_s[lrow];
        bf16* op = out + ((size_t)bI * SEQ + q0 + lrow) * CH + hI * HDIM + lc0;
#pragma unroll
        for (int c = 0; c < 16; c += 2) {
            bf16 t2[2] = { __float2bfloat16(Os[lrow * 68 + lc0 + c] * inv),
                           __float2bfloat16(Os[lrow * 68 + lc0 + c + 1] * inv) };
            *(uint32_t*)(op + c) = *(uint32_t*)t2;
        }
    }
}

// ---------------- Depthwise 3x3 conv + exact GELU (bf16 io) -----------------
__global__ void dwgelu_kernel(const bf16* __restrict__ h,
                              const float* __restrict__ w,
                              const float* __restrict__ bias,
                              bf16* __restrict__ out)
{
    int c = blockIdx.x * 256 + threadIdx.x;
    int n = blockIdx.y;
    int b = blockIdx.z;
    int hh = n >> 5, ww = n & 31;
    float acc = bias[c];
#pragma unroll
    for (int dy = -1; dy <= 1; dy++) {
        int y = hh + dy;
        if (y < 0 || y >= 32) continue;
#pragma unroll
        for (int dx = -1; dx <= 1; dx++) {
            int xw = ww + dx;
            if (xw < 0 || xw >= 32) continue;
            acc += __bfloat162float(h[((size_t)b * SEQ + y * 32 + xw) * HIDC + c])
                 * w[c * 9 + (dy + 1) * 3 + (dx + 1)];
        }
    }
    float gv = 0.5f * acc * (1.0f + erff(acc * 0.70710678118654752f));
    out[((size_t)b * SEQ + n) * HIDC + c] = __float2bfloat16(gv);
}

// ---------------- launch ----------------------------------------------------
extern "C" void kernel_launch(void* const* d_in, const int* in_sizes, int n_in,
                              void* d_out, int out_size)
{
    const float* x      = (const float*)d_in[0];
    const float* ln1_g  = (const float*)d_in[1];
    const float* ln1_b  = (const float*)d_in[2];
    const float* qkv_w  = (const float*)d_in[3];
    const float* proj_w = (const float*)d_in[4];
    const float* proj_b = (const float*)d_in[5];
    const float* ln2_g  = (const float*)d_in[6];
    const float* ln2_b  = (const float*)d_in[7];
    const float* fc1_w  = (const float*)d_in[8];
    const float* fc1_b  = (const float*)d_in[9];
    const float* dw_w   = (const float*)d_in[10];
    const float* dw_b   = (const float*)d_in[11];
    const float* fc2_w  = (const float*)d_in[12];
    const float* fc2_b  = (const float*)d_in[13];
    float* out = (float*)d_out;

    bf16 *wqkv, *wproj, *wfc1, *wfc2, *ln16, *qkv16, *at16, *h16, *h216;
    float *x1b;
    cudaGetSymbolAddress((void**)&wqkv,  g_wqkv);
    cudaGetSymbolAddress((void**)&wproj, g_wproj);
    cudaGetSymbolAddress((void**)&wfc1,  g_wfc1);
    cudaGetSymbolAddress((void**)&wfc2,  g_wfc2);
    cudaGetSymbolAddress((void**)&ln16,  g_ln16);
    cudaGetSymbolAddress((void**)&qkv16, g_qkv16);
    cudaGetSymbolAddress((void**)&at16,  g_at16);
    cudaGetSymbolAddress((void**)&x1b,   g_x1);
    cudaGetSymbolAddress((void**)&h16,   g_h16);
    cudaGetSymbolAddress((void**)&h216,  g_h216);

    cudaFuncSetAttribute(gemm_bf<float>,
                         cudaFuncAttributeMaxDynamicSharedMemorySize, GT_SMEM);
    cudaFuncSetAttribute(gemm_bf<bf16>,
                         cudaFuncAttributeMaxDynamicSharedMemorySize, GT_SMEM);
    cudaFuncSetAttribute(flash_bf,
                         cudaFuncAttributeMaxDynamicSharedMemorySize, FLASH_SMEM);

    // 0) weight conversion (fp32 -> bf16)
    to_bf16<<<(QKVW*CH)/1024, 256>>>(qkv_w,  wqkv);
    to_bf16<<<(CH*CH)/1024,   256>>>(proj_w, wproj);
    to_bf16<<<(HIDC*CH)/1024, 256>>>(fc1_w,  wfc1);
    to_bf16<<<(CH*HIDC)/1024, 256>>>(fc2_w,  wfc2);

    // 1) LN1 -> bf16
    ln_kernel<<<ROWS, 128>>>(x, ln1_g, ln1_b, ln16);

    // 2) QKV GEMM -> bf16
    gemm_bf<bf16><<<dim3(QKVW/128, ROWS/128), 256, GT_SMEM>>>(
        ln16, CH, wqkv, CH, nullptr, nullptr, 0, qkv16, QKVW, CH);

    // 3) flash attention -> bf16
    flash_bf<<<dim3(SEQ/64, BQ*NHD), 256, FLASH_SMEM>>>(qkv16, at16);

    // 4) x1 = x + o @ proj_w^T + proj_b   (fp32 out)
    gemm_bf<float><<<dim3(CH/128, ROWS/128), 256, GT_SMEM>>>(
        at16, CH, wproj, CH, proj_b, x, CH, x1b, CH, CH);

    // 5) LN2 -> bf16
    ln_kernel<<<ROWS, 128>>>(x1b, ln2_g, ln2_b, ln16);

    // 6) h = ln2 @ fc1_w^T + fc1_b -> bf16
    gemm_bf<bf16><<<dim3(HIDC/128, ROWS/128), 256, GT_SMEM>>>(
        ln16, CH, wfc1, CH, fc1_b, nullptr, 0, h16, HIDC, CH);

    // 7) depthwise conv + gelu -> bf16
    dwgelu_kernel<<<dim3(HIDC/256, SEQ, BQ), 256>>>(h16, dw_w, dw_b, h216);

    // 8) out = x1 + h2 @ fc2_w^T + fc2_b  (fp32 out)
    gemm_bf<float><<<dim3(CH/128, ROWS/128), 256, GT_SMEM>>>(
        h216, HIDC, wfc2, HIDC, fc2_b, x1b, CH, out, CH, HIDC);
}

// round 13
// speedup vs baseline: 1.3491x; 1.3491x over previous
#include <cuda_runtime.h>
#include <cuda_bf16.h>
#include <mma.h>
#include <math.h>
#include <stdint.h>

using namespace nvcuda;
typedef __nv_bfloat16 bf16;

// Problem constants
#define BQ   8
#define SEQ  1024
#define CH   512
#define HIDC 2048
#define NHD  8
#define HDIM 64
#define ROWS (BQ*SEQ)          // 8192
#define QKVW (3*CH)            // 1536

// ---------------- scratch ----------------------------------------------------
__device__ bf16  g_wqkv[QKVW*CH];
__device__ bf16  g_wproj[CH*CH];
__device__ bf16  g_wfc1[HIDC*CH];
__device__ bf16  g_wfc2[CH*HIDC];
__device__ bf16  g_ln16[ROWS*CH];
__device__ bf16  g_qkv16[(size_t)ROWS*QKVW];
__device__ bf16  g_at16[ROWS*CH];
__device__ float g_x1 [ROWS*CH];
__device__ bf16  g_h16 [(size_t)ROWS*HIDC];
__device__ bf16  g_h216[(size_t)ROWS*HIDC];

// ---------------- helpers ---------------------------------------------------
__device__ __forceinline__ uint32_t su32(const void* p) {
    uint32_t a;
    asm("{ .reg .u64 t; cvta.to.shared.u64 t, %1; cvt.u32.u64 %0, t; }"
        : "=r"(a) : "l"(p));
    return a;
}
#define CPA16(d, s) asm volatile("cp.async.cg.shared.global [%0], [%1], 16;" :: "r"(d), "l"(s))
#define CPCOMMIT()  asm volatile("cp.async.commit_group;" ::: "memory")
#define CPWAIT(n)   asm volatile("cp.async.wait_group %0;" :: "n"(n) : "memory")

__device__ __forceinline__ void mma_bf16(float c[4],
    uint32_t a0, uint32_t a1, uint32_t a2, uint32_t a3,
    uint32_t b0, uint32_t b1)
{
    asm volatile(
        "mma.sync.aligned.m16n8k16.row.col.f32.bf16.bf16.f32 "
        "{%0,%1,%2,%3}, {%4,%5,%6,%7}, {%8,%9}, {%0,%1,%2,%3};"
        : "+f"(c[0]), "+f"(c[1]), "+f"(c[2]), "+f"(c[3])
        : "r"(a0), "r"(a1), "r"(a2), "r"(a3), "r"(b0), "r"(b1));
}
__device__ __forceinline__ void ldsm4t(uint32_t r[4], uint32_t addr) {
    asm volatile("ldmatrix.sync.aligned.m8n8.x4.trans.shared.b16 {%0,%1,%2,%3}, [%4];"
                 : "=r"(r[0]), "=r"(r[1]), "=r"(r[2]), "=r"(r[3]) : "r"(addr));
}
__device__ __forceinline__ uint32_t packbf(float lo, float hi) {
    uint32_t r;
    asm("cvt.rn.bf16x2.f32 %0, %1, %2;" : "=r"(r) : "f"(hi), "f"(lo));
    return r;
}

// ---------------- fp32 -> bf16 convert --------------------------------------
__global__ void to_bf16(const float* __restrict__ s, bf16* __restrict__ d)
{
    size_t i = ((size_t)blockIdx.x * 256 + threadIdx.x) * 4;
    float4 v = *(const float4*)(s + i);
    bf16 t[4] = { __float2bfloat16(v.x), __float2bfloat16(v.y),
                  __float2bfloat16(v.z), __float2bfloat16(v.w) };
    *(uint2*)(d + i) = *(uint2*)t;
}

// ---------------- LayerNorm (fp32 in, bf16 out) -----------------------------
__global__ void ln_kernel(const float* __restrict__ x,
                          const float* __restrict__ g,
                          const float* __restrict__ b,
                          bf16* __restrict__ out)
{
    int row = blockIdx.x;
    const float* xr = x + (size_t)row * CH;
    bf16* orow = out + (size_t)row * CH;
    int t = threadIdx.x;
    float v[4];
    float s = 0.f;
#pragma unroll
    for (int i = 0; i < 4; i++) { v[i] = xr[t + i*128]; s += v[i]; }
    __shared__ float red[4];
#pragma unroll
    for (int o = 16; o > 0; o >>= 1) s += __shfl_xor_sync(0xffffffffu, s, o);
    if ((t & 31) == 0) red[t >> 5] = s;
    __syncthreads();
    float mean = (red[0] + red[1] + red[2] + red[3]) * (1.0f / CH);
    float vs = 0.f;
#pragma unroll
    for (int i = 0; i < 4; i++) { float d = v[i] - mean; vs += d * d; }
#pragma unroll
    for (int o = 16; o > 0; o >>= 1) vs += __shfl_xor_sync(0xffffffffu, vs, o);
    __syncthreads();
    if ((t & 31) == 0) red[t >> 5] = vs;
    __syncthreads();
    float var = (red[0] + red[1] + red[2] + red[3]) * (1.0f / CH);
    float rstd = rsqrtf(var + 1e-5f);
#pragma unroll
    for (int i = 0; i < 4; i++) {
        int c = t + i*128;
        orow[c] = __float2bfloat16((v[i] - mean) * rstd * g[c] + b[c]);
    }
}

// ---------------- bf16 WMMA GEMM, 2-stage cp.async (R10 proven) -------------
#define LDSB 72                 // bf16 elems per smem row (144B)
#define TILE_E (128*LDSB)
#define GT_SMEM (4*TILE_E*2)    // 73728

template<typename OutT>
__global__ __launch_bounds__(256, 2)
void gemm_bf(const bf16* __restrict__ A, int lda,
             const bf16* __restrict__ B, int ldb,
             const float* __restrict__ bias,
             const float* __restrict__ res, int ldres,
             OutT* __restrict__ out, int ldo, int K)
{
    extern __shared__ char dsmc[];
    bf16* As = (bf16*)dsmc;
    bf16* Bs = As + 2*TILE_E;

    int tid = threadIdx.x;
    int wid = tid >> 5;
    int wm = wid >> 2;
    int wn = wid & 3;
    int m0 = blockIdx.y * 128;
    int n0 = blockIdx.x * 128;

    wmma::fragment<wmma::accumulator, 16, 16, 16, float> fc[4][2];
#pragma unroll
    for (int i = 0; i < 4; i++)
#pragma unroll
        for (int j = 0; j < 2; j++)
            wmma::fill_fragment(fc[i][j], 0.0f);

    int lrow  = tid >> 1;
    int sbase = (tid & 1) * 4;

    int nK = K / 64;

#pragma unroll
    for (int j = 0; j < 4; j++) {
        int cseg = (sbase + j) * 8;
        CPA16(su32(&As[lrow * LDSB + cseg]), A + (size_t)(m0 + lrow) * lda + cseg);
        CPA16(su32(&Bs[lrow * LDSB + cseg]), B + (size_t)(n0 + lrow) * ldb + cseg);
    }
    CPCOMMIT();

    for (int kc = 0; kc < nK; kc++) {
        int cur = kc & 1;
        if (kc + 1 < nK) {
            int nxt = cur ^ 1;
            int k0 = (kc + 1) * 64;
#pragma unroll
            for (int j = 0; j < 4; j++) {
                int cseg = (sbase + j) * 8;
                CPA16(su32(&As[nxt * TILE_E + lrow * LDSB + cseg]),
                      A + (size_t)(m0 + lrow) * lda + k0 + cseg);
                CPA16(su32(&Bs[nxt * TILE_E + lrow * LDSB + cseg]),
                      B + (size_t)(n0 + lrow) * ldb + k0 + cseg);
            }
            CPCOMMIT();
            CPWAIT(1);
        } else {
            CPWAIT(0);
        }
        __syncthreads();

        bf16* Ac = As + cur * TILE_E;
        bf16* Bc = Bs + cur * TILE_E;
#pragma unroll
        for (int ks = 0; ks < 4; ks++) {
            wmma::fragment<wmma::matrix_a, 16, 16, 16, bf16, wmma::row_major> fa[4];
            wmma::fragment<wmma::matrix_b, 16, 16, 16, bf16, wmma::col_major> fb[2];
#pragma unroll
            for (int i = 0; i < 4; i++)
                wmma::load_matrix_sync(fa[i], &Ac[(wm * 64 + i * 16) * LDSB + ks * 16], LDSB);
#pragma unroll
            for (int j = 0; j < 2; j++)
                wmma::load_matrix_sync(fb[j], &Bc[(wn * 32 + j * 16) * LDSB + ks * 16], LDSB);
#pragma unroll
            for (int i = 0; i < 4; i++)
#pragma unroll
                for (int j = 0; j < 2; j++)
                    wmma::mma_sync(fc[i][j], fa[i], fb[j], fc[i][j]);
        }
        __syncthreads();
    }

    float* eps = (float*)dsmc;
#pragma unroll
    for (int i = 0; i < 4; i++)
#pragma unroll
        for (int j = 0; j < 2; j++)
            wmma::store_matrix_sync(&eps[(wm * 64 + i * 16) * 132 + wn * 32 + j * 16],
                                    fc[i][j], 132, wmma::mem_row_major);
    __syncthreads();

    int r = tid >> 1;
    int c0 = (tid & 1) * 64;
#pragma unroll
    for (int c = 0; c < 64; c += 4) {
        float4 v = *(float4*)&eps[r * 132 + c0 + c];
        int n = n0 + c0 + c;
        if (bias) {
            v.x += bias[n]; v.y += bias[n + 1]; v.z += bias[n + 2]; v.w += bias[n + 3];
        }
        if (res) {
            float4 rr = *(const float4*)(res + (size_t)(m0 + r) * ldres + n);
            v.x += rr.x; v.y += rr.y; v.z += rr.z; v.w += rr.w;
        }
        if constexpr (sizeof(OutT) == 4) {
            *(float4*)((float*)out + (size_t)(m0 + r) * ldo + n) = v;
        } else {
            bf16 t[4] = { __float2bfloat16(v.x), __float2bfloat16(v.y),
                          __float2bfloat16(v.z), __float2bfloat16(v.w) };
            *(uint2*)((bf16*)out + (size_t)(m0 + r) * ldo + n) = *(uint2*)t;
        }
    }
}

// ---------------- Flash attention: register-resident mma.sync ---------------
// CTA: 64 queries x one head; 128 threads (4 warps), warp = 16 query rows.
__global__ __launch_bounds__(128, 3)
void flash_reg(const bf16* __restrict__ qkv, bf16* __restrict__ out)
{
    __shared__ __align__(16) bf16 Qs[64 * LDSB];
    __shared__ __align__(16) bf16 Kb[2][64 * LDSB];
    __shared__ __align__(16) bf16 Vb[2][64 * LDSB];

    int bz = blockIdx.y;
    int bI = bz / NHD, hI = bz % NHD;
    int q0 = blockIdx.x * 64;
    const bf16* base = qkv + (size_t)bI * SEQ * QKVW + hI * 3 * HDIM;

    int tid = threadIdx.x;
    int wid = tid >> 5;
    int lane = tid & 31;
    int lr = tid >> 1;              // 0..63 (row for loads)
    int lc = (tid & 1) * 32;        // col base for loads

    auto issue_kv = [&](int t0) {
        int buf = (t0 >> 6) & 1;
        const bf16* kp = base + (size_t)(t0 + lr) * QKVW + HDIM + lc;
        const bf16* vp = base + (size_t)(t0 + lr) * QKVW + 2 * HDIM + lc;
#pragma unroll
        for (int j = 0; j < 4; j++) {
            CPA16(su32(&Kb[buf][lr * LDSB + lc + j * 8]), kp + j * 8);
            CPA16(su32(&Vb[buf][lr * LDSB + lc + j * 8]), vp + j * 8);
        }
        CPCOMMIT();
    };

    issue_kv(0);
    // Q -> smem : 32 cols per thread = 4 x uint4 (8 bf16 each)
    {
        const bf16* qp = base + (size_t)(q0 + lr) * QKVW + lc;
#pragma unroll
        for (int j = 0; j < 4; j++)
            *(uint4*)&Qs[lr * LDSB + lc + j * 8] = *(const uint4*)(qp + j * 8);
    }
    __syncthreads();

    // Q A-fragments (row-major m16k16), per warp rows wid*16..+15
    uint32_t qa[4][4];
    {
        int r0 = wid * 16 + (lane >> 2);
        int cb = (lane & 3) * 2;
#pragma unroll
        for (int kb = 0; kb < 4; kb++) {
            const bf16* qb = &Qs[0] + kb * 16 + cb;
            qa[kb][0] = *(const uint32_t*)(qb + (size_t)r0 * LDSB);
            qa[kb][1] = *(const uint32_t*)(qb + (size_t)(r0 + 8) * LDSB);
            qa[kb][2] = *(const uint32_t*)(qb + (size_t)r0 * LDSB + 8);
            qa[kb][3] = *(const uint32_t*)(qb + (size_t)(r0 + 8) * LDSB + 8);
        }
    }

    float oc[8][4];
#pragma unroll
    for (int nt = 0; nt < 8; nt++)
#pragma unroll
        for (int j = 0; j < 4; j++) oc[nt][j] = 0.f;
    float mrow[2] = { -1e30f, -1e30f };
    float lsum[2] = { 0.f, 0.f };

    int krow = lane >> 2;           // b-frag n index
    int kcol = (lane & 3) * 2;      // b-frag k offset
    int lmrow = (lane & 7) + ((lane >> 3) & 1) * 8;
    int lmcol = (lane >> 4) * 8;

    for (int t0 = 0; t0 < SEQ; t0 += 64) {
        CPWAIT(0);
        __syncthreads();
        if (t0 + 64 < SEQ) issue_kv(t0 + 64);

        int buf = (t0 >> 6) & 1;
        const bf16* Ks = Kb[buf];
        const bf16* Vs = Vb[buf];

        // ---- S = Q @ K^T : 8 n-tiles x 4 k-blocks
        float sc[8][4];
#pragma unroll
        for (int nt = 0; nt < 8; nt++)
#pragma unroll
            for (int j = 0; j < 4; j++) sc[nt][j] = 0.f;
#pragma unroll
        for (int kb = 0; kb < 4; kb++) {
#pragma unroll
            for (int nt = 0; nt < 8; nt++) {
                const bf16* kbp = Ks + (size_t)(nt * 8 + krow) * LDSB + kb * 16 + kcol;
                uint32_t b0 = *(const uint32_t*)(kbp);
                uint32_t b1 = *(const uint32_t*)(kbp + 8);
                mma_bf16(sc[nt], qa[kb][0], qa[kb][1], qa[kb][2], qa[kb][3], b0, b1);
            }
        }

        // ---- online softmax in registers (rows r0 = lane>>2, r1 = r0+8)
        float mx0 = -1e30f, mx1 = -1e30f;
#pragma unroll
        for (int nt = 0; nt < 8; nt++) {
            mx0 = fmaxf(mx0, fmaxf(sc[nt][0], sc[nt][1]));
            mx1 = fmaxf(mx1, fmaxf(sc[nt][2], sc[nt][3]));
        }
        mx0 *= 0.125f; mx1 *= 0.125f;
        mx0 = fmaxf(mx0, __shfl_xor_sync(0xffffffffu, mx0, 1));
        mx0 = fmaxf(mx0, __shfl_xor_sync(0xffffffffu, mx0, 2));
        mx1 = fmaxf(mx1, __shfl_xor_sync(0xffffffffu, mx1, 1));
        mx1 = fmaxf(mx1, __shfl_xor_sync(0xffffffffu, mx1, 2));

        float mn0 = fmaxf(mrow[0], mx0);
        float mn1 = fmaxf(mrow[1], mx1);
        float sf0 = __expf(mrow[0] - mn0);
        float sf1 = __expf(mrow[1] - mn1);
        mrow[0] = mn0; mrow[1] = mn1;

        float sum0 = 0.f, sum1 = 0.f;
#pragma unroll
        for (int nt = 0; nt < 8; nt++) {
            sc[nt][0] = __expf(sc[nt][0] * 0.125f - mn0);
            sc[nt][1] = __expf(sc[nt][1] * 0.125f - mn0);
            sc[nt][2] = __expf(sc[nt][2] * 0.125f - mn1);
            sc[nt][3] = __expf(sc[nt][3] * 0.125f - mn1);
            sum0 += sc[nt][0] + sc[nt][1];
            sum1 += sc[nt][2] + sc[nt][3];
        }
        sum0 += __shfl_xor_sync(0xffffffffu, sum0, 1);
        sum0 += __shfl_xor_sync(0xffffffffu, sum0, 2);
        sum1 += __shfl_xor_sync(0xffffffffu, sum1, 1);
        sum1 += __shfl_xor_sync(0xffffffffu, sum1, 2);
        lsum[0] = lsum[0] * sf0 + sum0;
        lsum[1] = lsum[1] * sf1 + sum1;

#pragma unroll
        for (int nt = 0; nt < 8; nt++) {
            oc[nt][0] *= sf0; oc[nt][1] *= sf0;
            oc[nt][2] *= sf1; oc[nt][3] *= sf1;
        }

        // ---- pack P into A-fragments
        uint32_t pa[4][4];
#pragma unroll
        for (int kb = 0; kb < 4; kb++) {
            pa[kb][0] = packbf(sc[2*kb][0],   sc[2*kb][1]);
            pa[kb][1] = packbf(sc[2*kb][2],   sc[2*kb][3]);
            pa[kb][2] = packbf(sc[2*kb+1][0], sc[2*kb+1][1]);
            pa[kb][3] = packbf(sc[2*kb+1][2], sc[2*kb+1][3]);
        }

        // ---- O += P @ V : V B-frags via ldmatrix.x4.trans
#pragma unroll
        for (int kb = 0; kb < 4; kb++) {
#pragma unroll
            for (int dg = 0; dg < 4; dg++) {
                uint32_t vr[4];
                uint32_t addr = su32(Vs + (size_t)(kb * 16 + lmrow) * LDSB + dg * 16 + lmcol);
                ldsm4t(vr, addr);
                mma_bf16(oc[2*dg],     pa[kb][0], pa[kb][1], pa[kb][2], pa[kb][3], vr[0], vr[1]);
                mma_bf16(oc[2*dg + 1], pa[kb][0], pa[kb][1], pa[kb][2], pa[kb][3], vr[2], vr[3]);
            }
        }
    }

    // ---- writeout O / l
    {
        float inv0 = 1.0f / lsum[0];
        float inv1 = 1.0f / lsum[1];
        int r0 = wid * 16 + (lane >> 2);
        int cb = (lane & 3) * 2;
        bf16* op0 = out + ((size_t)bI * SEQ + q0 + r0) * CH + hI * HDIM + cb;
        bf16* op1 = op0 + (size_t)8 * CH;
#pragma unroll
        for (int nt = 0; nt < 8; nt++) {
            *(uint32_t*)(op0 + nt * 8) = packbf(oc[nt][0] * inv0, oc[nt][1] * inv0);
            *(uint32_t*)(op1 + nt * 8) = packbf(oc[nt][2] * inv1, oc[nt][3] * inv1);
        }
    }
}

// ---------------- Depthwise 3x3 conv + exact GELU (bf16 io) -----------------
__global__ void dwgelu_kernel(const bf16* __restrict__ h,
                              const float* __restrict__ w,
                              const float* __restrict__ bias,
                              bf16* __restrict__ out)
{
    int c = blockIdx.x * 256 + threadIdx.x;
    int n = blockIdx.y;
    int b = blockIdx.z;
    int hh = n >> 5, ww = n & 31;
    float acc = bias[c];
#pragma unroll
    for (int dy = -1; dy <= 1; dy++) {
        int y = hh + dy;
        if (y < 0 || y >= 32) continue;
#pragma unroll
        for (int dx = -1; dx <= 1; dx++) {
            int xw = ww + dx;
            if (xw < 0 || xw >= 32) continue;
            acc += __bfloat162float(h[((size_t)b * SEQ + y * 32 + xw) * HIDC + c])
                 * w[c * 9 + (dy + 1) * 3 + (dx + 1)];
        }
    }
    float gv = 0.5f * acc * (1.0f + erff(acc * 0.70710678118654752f));
    out[((size_t)b * SEQ + n) * HIDC + c] = __float2bfloat16(gv);
}

// ---------------- launch ----------------------------------------------------
extern "C" void kernel_launch(void* const* d_in, const int* in_sizes, int n_in,
                              void* d_out, int out_size)
{
    const float* x      = (const float*)d_in[0];
    const float* ln1_g  = (const float*)d_in[1];
    const float* ln1_b  = (const float*)d_in[2];
    const float* qkv_w  = (const float*)d_in[3];
    const float* proj_w = (const float*)d_in[4];
    const float* proj_b = (const float*)d_in[5];
    const float* ln2_g  = (const float*)d_in[6];
    const float* ln2_b  = (const float*)d_in[7];
    const float* fc1_w  = (const float*)d_in[8];
    const float* fc1_b  = (const float*)d_in[9];
    const float* dw_w   = (const float*)d_in[10];
    const float* dw_b   = (const float*)d_in[11];
    const float* fc2_w  = (const float*)d_in[12];
    const float* fc2_b  = (const float*)d_in[13];
    float* out = (float*)d_out;

    bf16 *wqkv, *wproj, *wfc1, *wfc2, *ln16, *qkv16, *at16, *h16, *h216;
    float *x1b;
    cudaGetSymbolAddress((void**)&wqkv,  g_wqkv);
    cudaGetSymbolAddress((void**)&wproj, g_wproj);
    cudaGetSymbolAddress((void**)&wfc1,  g_wfc1);
    cudaGetSymbolAddress((void**)&wfc2,  g_wfc2);
    cudaGetSymbolAddress((void**)&ln16,  g_ln16);
    cudaGetSymbolAddress((void**)&qkv16, g_qkv16);
    cudaGetSymbolAddress((void**)&at16,  g_at16);
    cudaGetSymbolAddress((void**)&x1b,   g_x1);
    cudaGetSymbolAddress((void**)&h16,   g_h16);
    cudaGetSymbolAddress((void**)&h216,  g_h216);

    cudaFuncSetAttribute(gemm_bf<float>,
                         cudaFuncAttributeMaxDynamicSharedMemorySize, GT_SMEM);
    cudaFuncSetAttribute(gemm_bf<bf16>,
                         cudaFuncAttributeMaxDynamicSharedMemorySize, GT_SMEM);

    // 0) weight conversion (fp32 -> bf16)
    to_bf16<<<(QKVW*CH)/1024, 256>>>(qkv_w,  wqkv);
    to_bf16<<<(CH*CH)/1024,   256>>>(proj_w, wproj);
    to_bf16<<<(HIDC*CH)/1024, 256>>>(fc1_w,  wfc1);
    to_bf16<<<(CH*HIDC)/1024, 256>>>(fc2_w,  wfc2);

    // 1) LN1 -> bf16
    ln_kernel<<<ROWS, 128>>>(x, ln1_g, ln1_b, ln16);

    // 2) QKV GEMM -> bf16
    gemm_bf<bf16><<<dim3(QKVW/128, ROWS/128), 256, GT_SMEM>>>(
        ln16, CH, wqkv, CH, nullptr, nullptr, 0, qkv16, QKVW, CH);

    // 3) flash attention (register-resident) -> bf16
    flash_reg<<<dim3(SEQ/64, BQ*NHD), 128>>>(qkv16, at16);

    // 4) x1 = x + o @ proj_w^T + proj_b   (fp32 out)
    gemm_bf<float><<<dim3(CH/128, ROWS/128), 256, GT_SMEM>>>(
        at16, CH, wproj, CH, proj_b, x, CH, x1b, CH, CH);

    // 5) LN2 -> bf16
    ln_kernel<<<ROWS, 128>>>(x1b, ln2_g, ln2_b, ln16);

    // 6) h = ln2 @ fc1_w^T + fc1_b -> bf16
    gemm_bf<bf16><<<dim3(HIDC/128, ROWS/128), 256, GT_SMEM>>>(
        ln16, CH, wfc1, CH, fc1_b, nullptr, 0, h16, HIDC, CH);

    // 7) depthwise conv + gelu -> bf16
    dwgelu_kernel<<<dim3(HIDC/256, SEQ, BQ), 256>>>(h16, dw_w, dw_b, h216);

    // 8) out = x1 + h2 @ fc2_w^T + fc2_b  (fp32 out)
    gemm_bf<float><<<dim3(CH/128, ROWS/128), 256, GT_SMEM>>>(
        h216, HIDC, wfc2, HIDC, fc2_b, x1b, CH, out, CH, HIDC);
}